// round 14
// baseline (speedup 1.0000x reference)
#include <cuda_runtime.h>
#include <math.h>

#define NN_ 1536
#define DD_ 768
#define HH_ 64
#define PLANE (NN_ * NN_)
#define KSPLIT 12

// Scratch (fully overwritten every launch -> graph-replay safe)
__device__ float g_part[KSPLIT * NN_ * 128]; // k-split partials of E@[W1a|W1b]
__device__ float g_A[NN_ * HH_];             // ha - g
__device__ float g_B[NN_ * HH_];             // hb + g + b1
__device__ float g_pv[NN_ * 6];              // pos(3), vel(3)

__device__ __forceinline__ void cpa16(unsigned s, const void* g) {
    asm volatile("cp.async.cg.shared.global [%0], [%1], 16;" :: "r"(s), "l"(g));
}
template <int N>
__device__ __forceinline__ void cp_wait() {
    asm volatile("cp.async.wait_group %0;" :: "n"(N) : "memory");
}

// ---------------------------------------------------------------------------
// Kernel 1: partial GEMM, 4-stage cp.async pipeline. grid (24, KSPLIT), 256t.
// Round-12 configuration (measured 11.1us): no min-blocks cap, hoisted
// fill pointers. Per thread: 8 rows x 4 cols.
// ---------------------------------------------------------------------------
__global__ __launch_bounds__(256) void gemm_partial_kernel(
    const float* __restrict__ E, const float* __restrict__ W1)
{
    __shared__ __align__(16) float sE[4][64 * 16];
    __shared__ __align__(16) float sW[4][16 * 128];

    const int t    = threadIdx.x;
    const int rb   = blockIdx.x;
    const int ks   = blockIdx.y;
    const int lane = t & 31;
    const int wrp  = t >> 5;

    const int erow = t >> 2, ec4 = t & 3;
    const int kk1  = t >> 5, q   = t & 31;

    const unsigned se_b = (unsigned)__cvta_generic_to_shared(&sE[0][0]);
    const unsigned sw_b = (unsigned)__cvta_generic_to_shared(&sW[0][0]);

    // hoisted base pointers
    const float* ebase = E + (size_t)(rb * 64 + erow) * DD_ + ks * 64 + ec4 * 4;
    const float* wbase = (q < 16) ? W1 + (size_t)(ks * 64) * 64 + q * 4
                                  : W1 + (size_t)(DD_ + ks * 64) * 64 + (q - 16) * 4;

#pragma unroll
    for (int kt = 0; kt < 4; ++kt) {
        cpa16(se_b + (kt * 1024 + erow * 16 + ec4 * 4) * 4, ebase + kt * 16);
        cpa16(sw_b + (kt * 2048 + kk1 * 128 + q * 4) * 4,
              wbase + (size_t)(kt * 16 + kk1) * 64);
        cpa16(sw_b + (kt * 2048 + (kk1 + 8) * 128 + q * 4) * 4,
              wbase + (size_t)(kt * 16 + kk1 + 8) * 64);
        asm volatile("cp.async.commit_group;" ::: "memory");
    }

    float4 acc[8];
#pragma unroll
    for (int r = 0; r < 8; ++r) acc[r] = make_float4(0.f, 0.f, 0.f, 0.f);

#pragma unroll
    for (int kt = 0; kt < 4; ++kt) {
        if (kt == 0)      cp_wait<3>();
        else if (kt == 1) cp_wait<2>();
        else if (kt == 2) cp_wait<1>();
        else              cp_wait<0>();
        __syncthreads();

        const float4* sW4 = reinterpret_cast<const float4*>(sW[kt]);
        const float4* sE4 = reinterpret_cast<const float4*>(sE[kt]);
#pragma unroll
        for (int k4 = 0; k4 < 4; ++k4) {
            float4 w0 = sW4[(k4 * 4 + 0) * 32 + lane];
            float4 w1 = sW4[(k4 * 4 + 1) * 32 + lane];
            float4 w2 = sW4[(k4 * 4 + 2) * 32 + lane];
            float4 w3 = sW4[(k4 * 4 + 3) * 32 + lane];
#pragma unroll
            for (int r = 0; r < 8; ++r) {
                float4 e = sE4[(wrp * 8 + r) * 4 + k4];
                acc[r].x = fmaf(e.x, w0.x, acc[r].x);
                acc[r].y = fmaf(e.x, w0.y, acc[r].y);
                acc[r].z = fmaf(e.x, w0.z, acc[r].z);
                acc[r].w = fmaf(e.x, w0.w, acc[r].w);
                acc[r].x = fmaf(e.y, w1.x, acc[r].x);
                acc[r].y = fmaf(e.y, w1.y, acc[r].y);
                acc[r].z = fmaf(e.y, w1.z, acc[r].z);
                acc[r].w = fmaf(e.y, w1.w, acc[r].w);
                acc[r].x = fmaf(e.z, w2.x, acc[r].x);
                acc[r].y = fmaf(e.z, w2.y, acc[r].y);
                acc[r].z = fmaf(e.z, w2.z, acc[r].z);
                acc[r].w = fmaf(e.z, w2.w, acc[r].w);
                acc[r].x = fmaf(e.w, w3.x, acc[r].x);
                acc[r].y = fmaf(e.w, w3.y, acc[r].y);
                acc[r].z = fmaf(e.w, w3.z, acc[r].z);
                acc[r].w = fmaf(e.w, w3.w, acc[r].w);
            }
        }
    }

    float4* dst = reinterpret_cast<float4*>(g_part) + (size_t)ks * (NN_ * 32);
    const int rbase = rb * 64 + wrp * 8;
#pragma unroll
    for (int r = 0; r < 8; ++r)
        dst[(rbase + r) * 32 + lane] = acc[r];
}

// ---------------------------------------------------------------------------
// Kernel 2: reduce partials + fold geometry. grid 96, block (16,16).
// ---------------------------------------------------------------------------
__global__ __launch_bounds__(256) void fold_kernel(
    const float* __restrict__ pos, const float* __restrict__ prev,
    const float* __restrict__ W1, const float* __restrict__ b1)
{
    const int h4 = threadIdx.x;
    const int i  = blockIdx.x * 16 + threadIdx.y;

    const float4* P4 = reinterpret_cast<const float4*>(g_part);
    float4 sa = make_float4(0.f, 0.f, 0.f, 0.f);
    float4 sb = make_float4(0.f, 0.f, 0.f, 0.f);
#pragma unroll
    for (int s = 0; s < KSPLIT; ++s) {
        size_t base = ((size_t)s * (NN_ * 128) + (size_t)i * 128) >> 2;
        float4 va = P4[base + h4];
        float4 vb = P4[base + 16 + h4];
        sa.x += va.x; sa.y += va.y; sa.z += va.z; sa.w += va.w;
        sb.x += vb.x; sb.y += vb.y; sb.z += vb.z; sb.w += vb.w;
    }

    float px = pos[i * 3 + 0], py = pos[i * 3 + 1], pz = pos[i * 3 + 2];
    float vx = px - prev[i * 3 + 0];
    float vy = py - prev[i * 3 + 1];
    float vz = pz - prev[i * 3 + 2];

    const float4* Ws4 = reinterpret_cast<const float4*>(W1 + 2 * DD_ * 64);
    float4 w0 = Ws4[0 * 16 + h4], w1 = Ws4[1 * 16 + h4], w2 = Ws4[2 * 16 + h4];
    float4 w4 = Ws4[4 * 16 + h4], w5 = Ws4[5 * 16 + h4], w6 = Ws4[6 * 16 + h4];
    float4 w7 = Ws4[7 * 16 + h4];
    float4 b14 = reinterpret_cast<const float4*>(b1)[h4];

    float4 g;
    g.x = px*w0.x + py*w1.x + pz*w2.x + vx*w4.x + vy*w5.x + vz*w6.x + py*w7.x;
    g.y = px*w0.y + py*w1.y + pz*w2.y + vx*w4.y + vy*w5.y + vz*w6.y + py*w7.y;
    g.z = px*w0.z + py*w1.z + pz*w2.z + vx*w4.z + vy*w5.z + vz*w6.z + py*w7.z;
    g.w = px*w0.w + py*w1.w + pz*w2.w + vx*w4.w + vy*w5.w + vz*w6.w + py*w7.w;

    float4 outA = make_float4(sa.x - g.x, sa.y - g.y, sa.z - g.z, sa.w - g.w);
    float4 outB = make_float4(sb.x + g.x + b14.x, sb.y + g.y + b14.y,
                              sb.z + g.z + b14.z, sb.w + g.w + b14.w);
    reinterpret_cast<float4*>(g_A)[i * 16 + h4] = outA;
    reinterpret_cast<float4*>(g_B)[i * 16 + h4] = outB;

    if (h4 == 0) {
        g_pv[i * 6 + 0] = px; g_pv[i * 6 + 1] = py; g_pv[i * 6 + 2] = pz;
        g_pv[i * 6 + 3] = vx; g_pv[i * 6 + 4] = vy; g_pv[i * 6 + 5] = vz;
    }
}

// ---------------------------------------------------------------------------
// Kernel 3: pairwise, 4 CTAs/SM (round-13, at fma-pipe roofline). grid
// (48, 48), block (16, 16), tile 32x32, 2x2 micro-tile. A via broadcast LDG
// (L1-hot); B in smem; w3 packed in sW2d.w; h-loop fully unrolled.
// ---------------------------------------------------------------------------
#define PQ_STEP(dd, aa, bb, w3h, wdv, A1, A2, A3)          \
    {                                                       \
        float t_ = fmaf((dd), (w3h), (aa) + (bb));          \
        float r_ = fmaxf(t_, 0.f);                          \
        A1 = fmaf(r_, (wdv).x, A1);                         \
        A2 = fmaf(r_, (wdv).y, A2);                         \
        A3 = fmaf(r_, (wdv).z, A3);                         \
    }

#define H_COMP(a0c, a1c, b0c, b1c, wdv)                                \
    PQ_STEP(d0, a0c, b0c, (wdv).w, wdv, s1_0, s2_0, s3_0)              \
    PQ_STEP(d1, a0c, b1c, (wdv).w, wdv, s1_1, s2_1, s3_1)              \
    PQ_STEP(d2, a1c, b0c, (wdv).w, wdv, s1_2, s2_2, s3_2)              \
    PQ_STEP(d3, a1c, b1c, (wdv).w, wdv, s1_3, s2_3, s3_3)

__global__ __launch_bounds__(256, 4) void pair_kernel(
    const float* __restrict__ W1, const float* __restrict__ W2,
    const float* __restrict__ b2, float* __restrict__ out)
{
    __shared__ __align__(16) float sB[32 * 68];
    __shared__ __align__(16) float4 sW2d[64];     // (d1,d2,d3,w3) per h
    __shared__ float sPVi[32 * 6];
    __shared__ float sPVj[32 * 6];

    const int tx = threadIdx.x, ty = threadIdx.y;
    const int t  = ty * 16 + tx;
    const int i0 = blockIdx.y * 32;
    const int j0 = blockIdx.x * 32;

#pragma unroll
    for (int idx = t; idx < 512; idx += 256) {
        int r = idx >> 4, c = idx & 15;
        reinterpret_cast<float4*>(sB)[r * 17 + c] =
            reinterpret_cast<const float4*>(g_B)[(j0 + r) * 16 + c];
    }
    if (t < 64) {
        float w0 = W2[t * 4 + 0];
        sW2d[t] = make_float4(W2[t * 4 + 1] - w0, W2[t * 4 + 2] - w0,
                              W2[t * 4 + 3] - w0, W1[(2 * DD_ + 3) * 64 + t]);
    }
    if (t < 192) {
        sPVi[t] = g_pv[i0 * 6 + t];
        sPVj[t] = g_pv[j0 * 6 + t];
    }
    __syncthreads();

    float d0, d1, d2, d3;
    {
        float bx0 = sPVj[tx * 6 + 0], by0 = sPVj[tx * 6 + 1], bz0 = sPVj[tx * 6 + 2];
        float bx1 = sPVj[(tx + 16) * 6 + 0], by1 = sPVj[(tx + 16) * 6 + 1], bz1 = sPVj[(tx + 16) * 6 + 2];
#define DIST(ri, bx, by, bz, DST)                                          \
        {                                                                   \
            float rx = (bx) - sPVi[(ri) * 6 + 0];                           \
            float ry = (by) - sPVi[(ri) * 6 + 1];                           \
            float rz = (bz) - sPVi[(ri) * 6 + 2];                           \
            DST = sqrtf(rx * rx + ry * ry + rz * rz);                       \
        }
        DIST(ty,      bx0, by0, bz0, d0)  DIST(ty,      bx1, by1, bz1, d1)
        DIST(ty + 16, bx0, by0, bz0, d2)  DIST(ty + 16, bx1, by1, bz1, d3)
#undef DIST
    }

    float s1_0 = 0.f, s1_1 = 0.f, s1_2 = 0.f, s1_3 = 0.f;
    float s2_0 = 0.f, s2_1 = 0.f, s2_2 = 0.f, s2_3 = 0.f;
    float s3_0 = 0.f, s3_1 = 0.f, s3_2 = 0.f, s3_3 = 0.f;

    const float4* aRow0 = reinterpret_cast<const float4*>(g_A) + (i0 + ty) * 16;
    const float4* aRow1 = aRow0 + 16 * 16;
    const float4* B4s   = reinterpret_cast<const float4*>(sB);

#pragma unroll 16
    for (int h4 = 0; h4 < 16; ++h4) {
        float4 a0  = aRow0[h4];
        float4 a1  = aRow1[h4];
        float4 b0  = B4s[tx * 17 + h4];
        float4 b1v = B4s[(tx + 16) * 17 + h4];
        float4 wd0 = sW2d[h4 * 4 + 0];
        float4 wd1 = sW2d[h4 * 4 + 1];
        float4 wd2 = sW2d[h4 * 4 + 2];
        float4 wd3 = sW2d[h4 * 4 + 3];

        H_COMP(a0.x, a1.x, b0.x, b1v.x, wd0)
        H_COMP(a0.y, a1.y, b0.y, b1v.y, wd1)
        H_COMP(a0.z, a1.z, b0.z, b1v.z, wd2)
        H_COMP(a0.w, a1.w, b0.w, b1v.w, wd3)
    }

    float acc1[4] = {s1_0, s1_1, s1_2, s1_3};
    float acc2[4] = {s2_0, s2_1, s2_2, s2_3};
    float acc3[4] = {s3_0, s3_1, s3_2, s3_3};
    float dist[4] = {d0, d1, d2, d3};

    const float db1 = __ldg(&b2[1]) - __ldg(&b2[0]);
    const float db2 = __ldg(&b2[2]) - __ldg(&b2[0]);
    const float db3 = __ldg(&b2[3]) - __ldg(&b2[0]);

#pragma unroll
    for (int p = 0; p < 2; ++p) {
        const int ri = ty + p * 16;
        const float pix = sPVi[ri * 6 + 0], piy = sPVi[ri * 6 + 1], piz = sPVi[ri * 6 + 2];
        const float vix = sPVi[ri * 6 + 3], viy = sPVi[ri * 6 + 4], viz = sPVi[ri * 6 + 5];
#pragma unroll
        for (int q = 0; q < 2; ++q) {
            const int pq = p * 2 + q;
            const int rj = tx + q * 16;
            float rpx = sPVj[rj * 6 + 0] - pix;
            float rpy = sPVj[rj * 6 + 1] - piy;
            float rpz = sPVj[rj * 6 + 2] - piz;
            float rvx = sPVj[rj * 6 + 3] - vix;
            float rvy = sPVj[rj * 6 + 4] - viy;
            float rvz = sPVj[rj * 6 + 5] - viz;
            float dot = rpx * rvx + rpy * rvy + rpz * rvz;
            float d = dist[pq];
            float c = -dot / fmaxf(d, 1e-6f);
            float v = rpy;

            float l1 = acc1[pq] + db1;
            float l2 = acc2[pq] + db2;
            float l3 = acc3[pq] + db3;
            float m = fmaxf(fmaxf(0.f, l1), fmaxf(l2, l3));
            float sum = __expf(0.f - m) + __expf(l1 - m)
                      + __expf(l2 - m) + __expf(l3 - m);
            float conf = __fdividef(1.0f, sum);
            int best = 0; float bm = 0.f;
            if (l1 > bm) { bm = l1; best = 1; }
            if (l2 > bm) { bm = l2; best = 2; }
            if (l3 > bm) { bm = l3; best = 3; }

            bool near  = d < 0.25f;
            bool appr  = !near && (c > 0.05f);
            bool flee  = !near && !appr && (c < -0.05f);
            bool above = !near && !appr && !flee && (fabsf(v) > 0.3f) && (d < 0.5f);

            int rt = near ? 0 : (appr ? 1 : (flee ? 2 : (above ? 3 : best)));
            float co = conf;
            if (near)              co = fmaxf(co, 0.8f);
            else if (appr || flee) co = fmaxf(co, 0.6f);
            else if (above)        co = fmaxf(co, 0.5f);

            int ig = i0 + ri;
            int jg = j0 + rj;
            size_t off = (size_t)ig * NN_ + jg;
            out[off]             = (float)rt;
            out[PLANE + off]     = co;
            out[2 * PLANE + off] = (jg > ig && co > 0.3f) ? 1.0f : 0.0f;
        }
    }
}

extern "C" void kernel_launch(void* const* d_in, const int* in_sizes, int n_in,
                              void* d_out, int out_size)
{
    const float* E    = (const float*)d_in[0];
    const float* pos  = (const float*)d_in[1];
    const float* prev = (const float*)d_in[2];
    const float* W1   = (const float*)d_in[3];
    const float* b1   = (const float*)d_in[4];
    const float* W2   = (const float*)d_in[5];
    const float* b2   = (const float*)d_in[6];
    float* out = (float*)d_out;

    gemm_partial_kernel<<<dim3(24, KSPLIT), 256>>>(E, W1);
    fold_kernel<<<NN_ / 16, dim3(16, 16)>>>(pos, prev, W1, b1);
    pair_kernel<<<dim3(48, 48), dim3(16, 16)>>>(W1, W2, b2, out);
}

// round 15
// speedup vs baseline: 1.0106x; 1.0106x over previous
#include <cuda_runtime.h>
#include <math.h>

#define NN_ 1536
#define DD_ 768
#define HH_ 64
#define PLANE (NN_ * NN_)
#define KSPLIT 12

// Scratch (fully overwritten every launch -> graph-replay safe)
__device__ float g_part[KSPLIT * NN_ * 128]; // k-split partials of E@[W1a|W1b]
__device__ float g_A[NN_ * HH_];             // ha - g
__device__ float g_B[NN_ * HH_];             // hb + g + b1
__device__ float g_pv[NN_ * 6];              // pos(3), vel(3)

__device__ __forceinline__ void cpa16(unsigned s, const void* g) {
    asm volatile("cp.async.cg.shared.global [%0], [%1], 16;" :: "r"(s), "l"(g));
}
template <int N>
__device__ __forceinline__ void cp_wait() {
    asm volatile("cp.async.wait_group %0;" :: "n"(N) : "memory");
}

// ---------------------------------------------------------------------------
// Kernel 1: partial GEMM, 4-stage cp.async pipeline. grid (24, KSPLIT), 256t.
// 3 CTAs/SM: launch_bounds(256,3) (reg budget 85) + max-shared carveout set
// host-side (3 x 48KB = 144KB must fit the unified L1/smem).
// ---------------------------------------------------------------------------
__global__ __launch_bounds__(256, 3) void gemm_partial_kernel(
    const float* __restrict__ E, const float* __restrict__ W1)
{
    __shared__ __align__(16) float sE[4][64 * 16];
    __shared__ __align__(16) float sW[4][16 * 128];

    const int t    = threadIdx.x;
    const int rb   = blockIdx.x;
    const int ks   = blockIdx.y;
    const int lane = t & 31;
    const int wrp  = t >> 5;

    const int erow = t >> 2, ec4 = t & 3;
    const int kk1  = t >> 5, q   = t & 31;

    const unsigned se_b = (unsigned)__cvta_generic_to_shared(&sE[0][0]);
    const unsigned sw_b = (unsigned)__cvta_generic_to_shared(&sW[0][0]);

    // hoisted base pointers
    const float* ebase = E + (size_t)(rb * 64 + erow) * DD_ + ks * 64 + ec4 * 4;
    const float* wbase = (q < 16) ? W1 + (size_t)(ks * 64) * 64 + q * 4
                                  : W1 + (size_t)(DD_ + ks * 64) * 64 + (q - 16) * 4;

#pragma unroll
    for (int kt = 0; kt < 4; ++kt) {
        cpa16(se_b + (kt * 1024 + erow * 16 + ec4 * 4) * 4, ebase + kt * 16);
        cpa16(sw_b + (kt * 2048 + kk1 * 128 + q * 4) * 4,
              wbase + (size_t)(kt * 16 + kk1) * 64);
        cpa16(sw_b + (kt * 2048 + (kk1 + 8) * 128 + q * 4) * 4,
              wbase + (size_t)(kt * 16 + kk1 + 8) * 64);
        asm volatile("cp.async.commit_group;" ::: "memory");
    }

    float4 acc[8];
#pragma unroll
    for (int r = 0; r < 8; ++r) acc[r] = make_float4(0.f, 0.f, 0.f, 0.f);

#pragma unroll
    for (int kt = 0; kt < 4; ++kt) {
        if (kt == 0)      cp_wait<3>();
        else if (kt == 1) cp_wait<2>();
        else if (kt == 2) cp_wait<1>();
        else              cp_wait<0>();
        __syncthreads();

        const float4* sW4 = reinterpret_cast<const float4*>(sW[kt]);
        const float4* sE4 = reinterpret_cast<const float4*>(sE[kt]);
#pragma unroll
        for (int k4 = 0; k4 < 4; ++k4) {
            float4 w0 = sW4[(k4 * 4 + 0) * 32 + lane];
            float4 w1 = sW4[(k4 * 4 + 1) * 32 + lane];
            float4 w2 = sW4[(k4 * 4 + 2) * 32 + lane];
            float4 w3 = sW4[(k4 * 4 + 3) * 32 + lane];
#pragma unroll
            for (int r = 0; r < 8; ++r) {
                float4 e = sE4[(wrp * 8 + r) * 4 + k4];
                acc[r].x = fmaf(e.x, w0.x, acc[r].x);
                acc[r].y = fmaf(e.x, w0.y, acc[r].y);
                acc[r].z = fmaf(e.x, w0.z, acc[r].z);
                acc[r].w = fmaf(e.x, w0.w, acc[r].w);
                acc[r].x = fmaf(e.y, w1.x, acc[r].x);
                acc[r].y = fmaf(e.y, w1.y, acc[r].y);
                acc[r].z = fmaf(e.y, w1.z, acc[r].z);
                acc[r].w = fmaf(e.y, w1.w, acc[r].w);
                acc[r].x = fmaf(e.z, w2.x, acc[r].x);
                acc[r].y = fmaf(e.z, w2.y, acc[r].y);
                acc[r].z = fmaf(e.z, w2.z, acc[r].z);
                acc[r].w = fmaf(e.z, w2.w, acc[r].w);
                acc[r].x = fmaf(e.w, w3.x, acc[r].x);
                acc[r].y = fmaf(e.w, w3.y, acc[r].y);
                acc[r].z = fmaf(e.w, w3.z, acc[r].z);
                acc[r].w = fmaf(e.w, w3.w, acc[r].w);
            }
        }
    }

    float4* dst = reinterpret_cast<float4*>(g_part) + (size_t)ks * (NN_ * 32);
    const int rbase = rb * 64 + wrp * 8;
#pragma unroll
    for (int r = 0; r < 8; ++r)
        dst[(rbase + r) * 32 + lane] = acc[r];
}

// ---------------------------------------------------------------------------
// Kernel 2: reduce partials + fold geometry. grid 96, block (16,16).
// ---------------------------------------------------------------------------
__global__ __launch_bounds__(256) void fold_kernel(
    const float* __restrict__ pos, const float* __restrict__ prev,
    const float* __restrict__ W1, const float* __restrict__ b1)
{
    const int h4 = threadIdx.x;
    const int i  = blockIdx.x * 16 + threadIdx.y;

    const float4* P4 = reinterpret_cast<const float4*>(g_part);
    float4 sa = make_float4(0.f, 0.f, 0.f, 0.f);
    float4 sb = make_float4(0.f, 0.f, 0.f, 0.f);
#pragma unroll
    for (int s = 0; s < KSPLIT; ++s) {
        size_t base = ((size_t)s * (NN_ * 128) + (size_t)i * 128) >> 2;
        float4 va = P4[base + h4];
        float4 vb = P4[base + 16 + h4];
        sa.x += va.x; sa.y += va.y; sa.z += va.z; sa.w += va.w;
        sb.x += vb.x; sb.y += vb.y; sb.z += vb.z; sb.w += vb.w;
    }

    float px = pos[i * 3 + 0], py = pos[i * 3 + 1], pz = pos[i * 3 + 2];
    float vx = px - prev[i * 3 + 0];
    float vy = py - prev[i * 3 + 1];
    float vz = pz - prev[i * 3 + 2];

    const float4* Ws4 = reinterpret_cast<const float4*>(W1 + 2 * DD_ * 64);
    float4 w0 = Ws4[0 * 16 + h4], w1 = Ws4[1 * 16 + h4], w2 = Ws4[2 * 16 + h4];
    float4 w4 = Ws4[4 * 16 + h4], w5 = Ws4[5 * 16 + h4], w6 = Ws4[6 * 16 + h4];
    float4 w7 = Ws4[7 * 16 + h4];
    float4 b14 = reinterpret_cast<const float4*>(b1)[h4];

    float4 g;
    g.x = px*w0.x + py*w1.x + pz*w2.x + vx*w4.x + vy*w5.x + vz*w6.x + py*w7.x;
    g.y = px*w0.y + py*w1.y + pz*w2.y + vx*w4.y + vy*w5.y + vz*w6.y + py*w7.y;
    g.z = px*w0.z + py*w1.z + pz*w2.z + vx*w4.z + vy*w5.z + vz*w6.z + py*w7.z;
    g.w = px*w0.w + py*w1.w + pz*w2.w + vx*w4.w + vy*w5.w + vz*w6.w + py*w7.w;

    float4 outA = make_float4(sa.x - g.x, sa.y - g.y, sa.z - g.z, sa.w - g.w);
    float4 outB = make_float4(sb.x + g.x + b14.x, sb.y + g.y + b14.y,
                              sb.z + g.z + b14.z, sb.w + g.w + b14.w);
    reinterpret_cast<float4*>(g_A)[i * 16 + h4] = outA;
    reinterpret_cast<float4*>(g_B)[i * 16 + h4] = outB;

    if (h4 == 0) {
        g_pv[i * 6 + 0] = px; g_pv[i * 6 + 1] = py; g_pv[i * 6 + 2] = pz;
        g_pv[i * 6 + 3] = vx; g_pv[i * 6 + 4] = vy; g_pv[i * 6 + 5] = vz;
    }
}

// ---------------------------------------------------------------------------
// Kernel 3: pairwise, 4 CTAs/SM (at fma-pipe roofline). grid (48, 48),
// block (16, 16), tile 32x32, 2x2 micro-tile. A via broadcast LDG (L1-hot);
// B in smem; w3 packed in sW2d.w; h-loop fully unrolled.
// ---------------------------------------------------------------------------
#define PQ_STEP(dd, aa, bb, w3h, wdv, A1, A2, A3)          \
    {                                                       \
        float t_ = fmaf((dd), (w3h), (aa) + (bb));          \
        float r_ = fmaxf(t_, 0.f);                          \
        A1 = fmaf(r_, (wdv).x, A1);                         \
        A2 = fmaf(r_, (wdv).y, A2);                         \
        A3 = fmaf(r_, (wdv).z, A3);                         \
    }

#define H_COMP(a0c, a1c, b0c, b1c, wdv)                                \
    PQ_STEP(d0, a0c, b0c, (wdv).w, wdv, s1_0, s2_0, s3_0)              \
    PQ_STEP(d1, a0c, b1c, (wdv).w, wdv, s1_1, s2_1, s3_1)              \
    PQ_STEP(d2, a1c, b0c, (wdv).w, wdv, s1_2, s2_2, s3_2)              \
    PQ_STEP(d3, a1c, b1c, (wdv).w, wdv, s1_3, s2_3, s3_3)

__global__ __launch_bounds__(256, 4) void pair_kernel(
    const float* __restrict__ W1, const float* __restrict__ W2,
    const float* __restrict__ b2, float* __restrict__ out)
{
    __shared__ __align__(16) float sB[32 * 68];
    __shared__ __align__(16) float4 sW2d[64];     // (d1,d2,d3,w3) per h
    __shared__ float sPVi[32 * 6];
    __shared__ float sPVj[32 * 6];

    const int tx = threadIdx.x, ty = threadIdx.y;
    const int t  = ty * 16 + tx;
    const int i0 = blockIdx.y * 32;
    const int j0 = blockIdx.x * 32;

#pragma unroll
    for (int idx = t; idx < 512; idx += 256) {
        int r = idx >> 4, c = idx & 15;
        reinterpret_cast<float4*>(sB)[r * 17 + c] =
            reinterpret_cast<const float4*>(g_B)[(j0 + r) * 16 + c];
    }
    if (t < 64) {
        float w0 = W2[t * 4 + 0];
        sW2d[t] = make_float4(W2[t * 4 + 1] - w0, W2[t * 4 + 2] - w0,
                              W2[t * 4 + 3] - w0, W1[(2 * DD_ + 3) * 64 + t]);
    }
    if (t < 192) {
        sPVi[t] = g_pv[i0 * 6 + t];
        sPVj[t] = g_pv[j0 * 6 + t];
    }
    __syncthreads();

    float d0, d1, d2, d3;
    {
        float bx0 = sPVj[tx * 6 + 0], by0 = sPVj[tx * 6 + 1], bz0 = sPVj[tx * 6 + 2];
        float bx1 = sPVj[(tx + 16) * 6 + 0], by1 = sPVj[(tx + 16) * 6 + 1], bz1 = sPVj[(tx + 16) * 6 + 2];
#define DIST(ri, bx, by, bz, DST)                                          \
        {                                                                   \
            float rx = (bx) - sPVi[(ri) * 6 + 0];                           \
            float ry = (by) - sPVi[(ri) * 6 + 1];                           \
            float rz = (bz) - sPVi[(ri) * 6 + 2];                           \
            DST = sqrtf(rx * rx + ry * ry + rz * rz);                       \
        }
        DIST(ty,      bx0, by0, bz0, d0)  DIST(ty,      bx1, by1, bz1, d1)
        DIST(ty + 16, bx0, by0, bz0, d2)  DIST(ty + 16, bx1, by1, bz1, d3)
#undef DIST
    }

    float s1_0 = 0.f, s1_1 = 0.f, s1_2 = 0.f, s1_3 = 0.f;
    float s2_0 = 0.f, s2_1 = 0.f, s2_2 = 0.f, s2_3 = 0.f;
    float s3_0 = 0.f, s3_1 = 0.f, s3_2 = 0.f, s3_3 = 0.f;

    const float4* aRow0 = reinterpret_cast<const float4*>(g_A) + (i0 + ty) * 16;
    const float4* aRow1 = aRow0 + 16 * 16;
    const float4* B4s   = reinterpret_cast<const float4*>(sB);

#pragma unroll 16
    for (int h4 = 0; h4 < 16; ++h4) {
        float4 a0  = aRow0[h4];
        float4 a1  = aRow1[h4];
        float4 b0  = B4s[tx * 17 + h4];
        float4 b1v = B4s[(tx + 16) * 17 + h4];
        float4 wd0 = sW2d[h4 * 4 + 0];
        float4 wd1 = sW2d[h4 * 4 + 1];
        float4 wd2 = sW2d[h4 * 4 + 2];
        float4 wd3 = sW2d[h4 * 4 + 3];

        H_COMP(a0.x, a1.x, b0.x, b1v.x, wd0)
        H_COMP(a0.y, a1.y, b0.y, b1v.y, wd1)
        H_COMP(a0.z, a1.z, b0.z, b1v.z, wd2)
        H_COMP(a0.w, a1.w, b0.w, b1v.w, wd3)
    }

    float acc1[4] = {s1_0, s1_1, s1_2, s1_3};
    float acc2[4] = {s2_0, s2_1, s2_2, s2_3};
    float acc3[4] = {s3_0, s3_1, s3_2, s3_3};
    float dist[4] = {d0, d1, d2, d3};

    const float db1 = __ldg(&b2[1]) - __ldg(&b2[0]);
    const float db2 = __ldg(&b2[2]) - __ldg(&b2[0]);
    const float db3 = __ldg(&b2[3]) - __ldg(&b2[0]);

#pragma unroll
    for (int p = 0; p < 2; ++p) {
        const int ri = ty + p * 16;
        const float pix = sPVi[ri * 6 + 0], piy = sPVi[ri * 6 + 1], piz = sPVi[ri * 6 + 2];
        const float vix = sPVi[ri * 6 + 3], viy = sPVi[ri * 6 + 4], viz = sPVi[ri * 6 + 5];
#pragma unroll
        for (int q = 0; q < 2; ++q) {
            const int pq = p * 2 + q;
            const int rj = tx + q * 16;
            float rpx = sPVj[rj * 6 + 0] - pix;
            float rpy = sPVj[rj * 6 + 1] - piy;
            float rpz = sPVj[rj * 6 + 2] - piz;
            float rvx = sPVj[rj * 6 + 3] - vix;
            float rvy = sPVj[rj * 6 + 4] - viy;
            float rvz = sPVj[rj * 6 + 5] - viz;
            float dot = rpx * rvx + rpy * rvy + rpz * rvz;
            float d = dist[pq];
            float c = -dot / fmaxf(d, 1e-6f);
            float v = rpy;

            float l1 = acc1[pq] + db1;
            float l2 = acc2[pq] + db2;
            float l3 = acc3[pq] + db3;
            float m = fmaxf(fmaxf(0.f, l1), fmaxf(l2, l3));
            float sum = __expf(0.f - m) + __expf(l1 - m)
                      + __expf(l2 - m) + __expf(l3 - m);
            float conf = __fdividef(1.0f, sum);
            int best = 0; float bm = 0.f;
            if (l1 > bm) { bm = l1; best = 1; }
            if (l2 > bm) { bm = l2; best = 2; }
            if (l3 > bm) { bm = l3; best = 3; }

            bool near  = d < 0.25f;
            bool appr  = !near && (c > 0.05f);
            bool flee  = !near && !appr && (c < -0.05f);
            bool above = !near && !appr && !flee && (fabsf(v) > 0.3f) && (d < 0.5f);

            int rt = near ? 0 : (appr ? 1 : (flee ? 2 : (above ? 3 : best)));
            float co = conf;
            if (near)              co = fmaxf(co, 0.8f);
            else if (appr || flee) co = fmaxf(co, 0.6f);
            else if (above)        co = fmaxf(co, 0.5f);

            int ig = i0 + ri;
            int jg = j0 + rj;
            size_t off = (size_t)ig * NN_ + jg;
            out[off]             = (float)rt;
            out[PLANE + off]     = co;
            out[2 * PLANE + off] = (jg > ig && co > 0.3f) ? 1.0f : 0.0f;
        }
    }
}

extern "C" void kernel_launch(void* const* d_in, const int* in_sizes, int n_in,
                              void* d_out, int out_size)
{
    const float* E    = (const float*)d_in[0];
    const float* pos  = (const float*)d_in[1];
    const float* prev = (const float*)d_in[2];
    const float* W1   = (const float*)d_in[3];
    const float* b1   = (const float*)d_in[4];
    const float* W2   = (const float*)d_in[5];
    const float* b2   = (const float*)d_in[6];
    float* out = (float*)d_out;

    // Request maximum shared-memory carveout so 3 x 48KB CTAs fit per SM.
    // Host-side attribute set: idempotent, deterministic, allocation-free.
    cudaFuncSetAttribute(gemm_partial_kernel,
                         cudaFuncAttributePreferredSharedMemoryCarveout,
                         cudaSharedmemCarveoutMaxShared);

    gemm_partial_kernel<<<dim3(24, KSPLIT), 256>>>(E, W1);
    fold_kernel<<<NN_ / 16, dim3(16, 16)>>>(pos, prev, W1, b1);
    pair_kernel<<<dim3(48, 48), dim3(16, 16)>>>(W1, W2, b2, out);
}